// round 5
// baseline (speedup 1.0000x reference)
#include <cuda_runtime.h>
#include <cstdint>
#include <math.h>

#define SEQ 512
#define BATCH 128
#define INDIM 256
#define HIDDIM 512
#define OUTDIM 256
#define K0 768
#define K1 1024
#define NBLK 128
#define NTHR 256
#define KT 64
#define NT0 12
#define NT1 16
#define TILE_FLOATS (KT*BATCH)      /* 8192 */

#define SM_W0_BYTES (K0*4*16)       /* 49152  */
#define SM_W1_BYTES (K1*4*16)       /* 65536  */
#define SM_IN_OFF   (SM_W0_BYTES + SM_W1_BYTES)      /* 114688 */
#define SMEM_BYTES  (SM_IN_OFF + 2*TILE_FLOATS*4)    /* 180224 */

__device__ float g_xT[(size_t)SEQ*INDIM*BATCH];   /* [t][k][b] */
__device__ float g_h0[2][HIDDIM*BATCH];           /* [phase][j][b] */
__device__ float g_h1[2][HIDDIM*BATCH];
__device__ unsigned g_cnt;
__device__ unsigned g_gen;

typedef unsigned long long ull;

__device__ __forceinline__ ull PK(float x, float y){
    ull r; asm("mov.b64 %0, {%1, %2};" : "=l"(r) : "f"(x), "f"(y)); return r;
}
__device__ __forceinline__ float2 UPK(ull a){
    float2 f; asm("mov.b64 {%0, %1}, %2;" : "=f"(f.x), "=f"(f.y) : "l"(a)); return f;
}
#define FMA2(acc,a,w) asm("fma.rn.f32x2 %0, %1, %2, %0;" : "+l"(acc) : "l"(a), "l"(w))

__device__ __forceinline__ void cpa16(float* dst, const float* src){
    unsigned d = (unsigned)__cvta_generic_to_shared(dst);
    asm volatile("cp.async.cg.shared.global [%0], [%1], 16;" :: "r"(d), "l"(src) : "memory");
}
#define CP_COMMIT() asm volatile("cp.async.commit_group;" ::: "memory")
#define CP_WAIT0()  asm volatile("cp.async.wait_group 0;" ::: "memory")

__device__ __forceinline__ void stage_tile(float* dst, const float* src, int tid){
    #pragma unroll
    for (int i = 0; i < 8; i++){
        int off = (i*NTHR + tid) * 4;
        cpa16(dst + off, src + off);
    }
    CP_COMMIT();
}

__device__ __forceinline__ float sigf(float x){ return 1.0f/(1.0f+expf(-x)); }

__device__ __forceinline__ void grid_sync(){
    __syncthreads();
    if (threadIdx.x == 0){
        volatile unsigned* vg = &g_gen;
        unsigned gen = *vg;
        __threadfence();
        if (atomicAdd(&g_cnt, 1u) == NBLK-1u){
            atomicExch(&g_cnt, 0u);
            __threadfence();
            atomicAdd(&g_gen, 1u);
        } else {
            while (*vg == gen) { __nanosleep(20); }
        }
        __threadfence();
    }
    __syncthreads();
}

/* x [t][b][k] -> g_xT [t][k][b] */
__global__ void transpose_x(const float* __restrict__ x){
    __shared__ float tile[32][33];
    int t = blockIdx.x, k0 = blockIdx.y*32, b0 = blockIdx.z*32;
    const float* src = x + (size_t)t*BATCH*INDIM;
    #pragma unroll
    for (int i = threadIdx.y; i < 32; i += 8)
        tile[i][threadIdx.x] = src[(size_t)(b0+i)*INDIM + k0 + threadIdx.x];
    __syncthreads();
    float* dst = g_xT + (size_t)t*INDIM*BATCH;
    #pragma unroll
    for (int i = threadIdx.y; i < 32; i += 8)
        dst[(size_t)(k0+i)*BATCH + b0 + threadIdx.x] = tile[threadIdx.x][i];
}

__global__ void __launch_bounds__(NTHR, 1) lstm_persist(
    const float* __restrict__ Wg0, const float* __restrict__ bg0,
    const float* __restrict__ Wg1, const float* __restrict__ bg1,
    const float* __restrict__ W_out, const float* __restrict__ b_out,
    float* __restrict__ out)
{
    extern __shared__ char smem[];
    ulonglong2* wS0 = (ulonglong2*)smem;                      /* [(k*4+jl)] = {(wf,wi),(wc,wo)} */
    ulonglong2* wS1 = (ulonglong2*)(smem + SM_W0_BYTES);
    float*      inS = (float*)(smem + SM_IN_OFF);             /* 2 x [KT][BATCH] */

    const int tid = threadIdx.x, bid = blockIdx.x;
    const int jl  = tid >> 6;          /* local unit 0..3 */
    const int p   = tid & 63;          /* batch pair: batches 2p, 2p+1 */
    const int u   = bid*4 + jl;        /* global hidden unit */

    /* ---- weights -> smem, pre-packed gate pairs ---- */
    for (int idx = tid; idx < K0*4; idx += NTHR){
        int k = idx >> 2, uu = bid*4 + (idx & 3);
        float wf = Wg0[(size_t)(0*HIDDIM+uu)*K0 + k];
        float wi = Wg0[(size_t)(1*HIDDIM+uu)*K0 + k];
        float wc = Wg0[(size_t)(2*HIDDIM+uu)*K0 + k];
        float wo = Wg0[(size_t)(3*HIDDIM+uu)*K0 + k];
        wS0[idx] = make_ulonglong2(PK(wf,wi), PK(wc,wo));
    }
    for (int idx = tid; idx < K1*4; idx += NTHR){
        int k = idx >> 2, uu = bid*4 + (idx & 3);
        float wf = Wg1[(size_t)(0*HIDDIM+uu)*K1 + k];
        float wi = Wg1[(size_t)(1*HIDDIM+uu)*K1 + k];
        float wc = Wg1[(size_t)(2*HIDDIM+uu)*K1 + k];
        float wo = Wg1[(size_t)(3*HIDDIM+uu)*K1 + k];
        wS1[idx] = make_ulonglong2(PK(wf,wi), PK(wc,wo));
    }

    const ull b0fi = PK(bg0[u],          bg0[HIDDIM+u]);
    const ull b0co = PK(bg0[2*HIDDIM+u], bg0[3*HIDDIM+u]);
    const ull b1fi = PK(bg1[u],          bg1[HIDDIM+u]);
    const ull b1co = PK(bg1[2*HIDDIM+u], bg1[3*HIDDIM+u]);

    float C0x=0.f,C0y=0.f,C1x=0.f,C1y=0.f;
    float h0x=0.f,h0y=0.f,h1x=0.f,h1y=0.f;

    /* zero this block's slices of both phases (fresh every launch/replay) */
    {
        float2 z = make_float2(0.f, 0.f);
        int o2 = u*BATCH + 2*p;
        *(float2*)(g_h0[0]+o2) = z; *(float2*)(g_h0[1]+o2) = z;
        *(float2*)(g_h1[0]+o2) = z; *(float2*)(g_h1[1]+o2) = z;
    }
    grid_sync();

    const int oo = bid*2 + ((tid >> 6) & 1);     /* output column, valid for tid<128 */
    const size_t OB = (size_t)SEQ*BATCH*OUTDIM;  /* 16777216 */

    for (int t = 0; t < SEQ; t++){
        const int cw = t & 1, pv = cw ^ 1;

        /* ================= layer 0 ================= */
        const float* xb  = g_xT + (size_t)t*INDIM*BATCH;
        const float* h0p = g_h0[pv];
        ull aA=b0fi, aB=b0co, aC=b0fi, aD=b0co;

        stage_tile(inS, xb, tid);
        for (int kt = 0; kt < NT0; kt++){
            CP_WAIT0();
            __syncthreads();
            if (kt+1 < NT0){
                const float* s = (kt+1 < 4) ? xb + (kt+1)*TILE_FLOATS
                                            : h0p + (kt+1-4)*TILE_FLOATS;
                stage_tile(inS + ((kt+1)&1)*TILE_FLOATS, s, tid);
            }
            const ulonglong2* wp = wS0 + kt*KT*4 + jl;
            const float* ip = inS + (kt&1)*TILE_FLOATS + 2*p;
            #pragma unroll 8
            for (int kk = 0; kk < KT; kk++){
                float2 v = *(const float2*)(ip + kk*BATCH);
                ulonglong2 w = wp[kk*4];
                ull a0 = PK(v.x, v.x), a1 = PK(v.y, v.y);
                FMA2(aA, a0, w.x); FMA2(aB, a0, w.y);
                FMA2(aC, a1, w.x); FMA2(aD, a1, w.y);
            }
        }
        {
            float2 fi0=UPK(aA), co0=UPK(aB), fi1=UPK(aC), co1=UPK(aD);
            C0x = sigf(fi0.x)*C0x + sigf(fi0.y)*tanhf(co0.x);
            h0x = sigf(co0.y)*tanhf(C0x);
            C0y = sigf(fi1.x)*C0y + sigf(fi1.y)*tanhf(co1.x);
            h0y = sigf(co1.y)*tanhf(C0y);
            *(float2*)(g_h0[cw] + u*BATCH + 2*p) = make_float2(h0x, h0y);
        }

        grid_sync();   /* the single per-step barrier */

        /* ========= layer 1  (+ fused out[t-1]) ========= */
        const float* h0c = g_h0[cw];
        const float* h1p = g_h1[pv];
        aA=b1fi; aB=b1co; aC=b1fi; aD=b1co;
        ull oacc = 0;

        stage_tile(inS, h0c, tid);
        for (int kt = 0; kt < NT1; kt++){
            CP_WAIT0();
            __syncthreads();
            if (kt+1 < NT1){
                const float* s = (kt+1 < 8) ? h0c + (kt+1)*TILE_FLOATS
                                            : h1p + (kt+1-8)*TILE_FLOATS;
                stage_tile(inS + ((kt+1)&1)*TILE_FLOATS, s, tid);
            }
            const ulonglong2* wp = wS1 + kt*KT*4 + jl;
            const float* ip = inS + (kt&1)*TILE_FLOATS + 2*p;
            #pragma unroll 8
            for (int kk = 0; kk < KT; kk++){
                float2 v = *(const float2*)(ip + kk*BATCH);
                ulonglong2 w = wp[kk*4];
                ull a0 = PK(v.x, v.x), a1 = PK(v.y, v.y);
                FMA2(aA, a0, w.x); FMA2(aB, a0, w.y);
                FMA2(aC, a1, w.x); FMA2(aD, a1, w.y);
            }
            /* out[t-1] rides the h1[t-1] tiles already staged (kt 8..15) */
            if (kt >= 8 && t > 0 && tid < 128){
                const float* wob = W_out + (size_t)oo*HIDDIM + (kt-8)*KT;
                const float* ip2 = inS + (kt&1)*TILE_FLOATS + 2*p;
                #pragma unroll 8
                for (int kk = 0; kk < KT; kk++){
                    float2 v = *(const float2*)(ip2 + kk*BATCH);
                    float w = __ldg(wob + kk);
                    FMA2(oacc, PK(v.x, v.y), PK(w, w));
                }
            }
        }
        {
            float2 fi0=UPK(aA), co0=UPK(aB), fi1=UPK(aC), co1=UPK(aD);
            C1x = sigf(fi0.x)*C1x + sigf(fi0.y)*tanhf(co0.x);
            h1x = sigf(co0.y)*tanhf(C1x);
            C1y = sigf(fi1.x)*C1y + sigf(fi1.y)*tanhf(co1.x);
            h1y = sigf(co1.y)*tanhf(C1y);
            *(float2*)(g_h1[cw] + u*BATCH + 2*p) = make_float2(h1x, h1y);
        }
        if (t > 0 && tid < 128){
            float2 ov = UPK(oacc);
            float bo = b_out[oo];
            size_t ob = ((size_t)(t-1)*BATCH + 2*p)*OUTDIM + oo;
            out[ob]          = ov.x + bo;
            out[ob + OUTDIM] = ov.y + bo;
        }
    }

    grid_sync();
    /* out[SEQ-1] */
    if (tid < 128){
        ull oacc = 0;
        const float* h1f = g_h1[(SEQ-1)&1];
        const float* wob = W_out + (size_t)oo*HIDDIM;
        #pragma unroll 4
        for (int j = 0; j < HIDDIM; j++){
            float2 v = __ldcg((const float2*)(h1f + j*BATCH + 2*p));
            float w = __ldg(wob + j);
            FMA2(oacc, PK(v.x, v.y), PK(w, w));
        }
        float2 ov = UPK(oacc);
        float bo = b_out[oo];
        size_t ob = ((size_t)(SEQ-1)*BATCH + 2*p)*OUTDIM + oo;
        out[ob]          = ov.x + bo;
        out[ob + OUTDIM] = ov.y + bo;
    }
    /* final states: [B][HID] each, order h_0, C_0, h_1, C_1 */
    {
        size_t r0 = (size_t)(2*p)*HIDDIM + u;
        size_t r1 = (size_t)(2*p+1)*HIDDIM + u;
        out[OB          + r0] = h0x;  out[OB          + r1] = h0y;
        out[OB +  65536 + r0] = C0x;  out[OB +  65536 + r1] = C0y;
        out[OB + 131072 + r0] = h1x;  out[OB + 131072 + r1] = h1y;
        out[OB + 196608 + r0] = C1x;  out[OB + 196608 + r1] = C1y;
    }
}

extern "C" void kernel_launch(void* const* d_in, const int* in_sizes, int n_in,
                              void* d_out, int out_size)
{
    (void)in_sizes; (void)n_in; (void)out_size;
    const float* x     = (const float*)d_in[0];
    const float* Wg0   = (const float*)d_in[1];
    const float* bg0   = (const float*)d_in[2];
    const float* Wg1   = (const float*)d_in[3];
    const float* bg1   = (const float*)d_in[4];
    const float* W_out = (const float*)d_in[5];
    const float* b_out = (const float*)d_in[6];

    cudaFuncSetAttribute(lstm_persist,
                         cudaFuncAttributeMaxDynamicSharedMemorySize, SMEM_BYTES);

    transpose_x<<<dim3(SEQ, INDIM/32, BATCH/32), dim3(32, 8)>>>(x);
    lstm_persist<<<NBLK, NTHR, SMEM_BYTES>>>(Wg0, bg0, Wg1, bg1, W_out, b_out,
                                             (float*)d_out);
}

// round 8
// speedup vs baseline: 1.1604x; 1.1604x over previous
#include <cuda_runtime.h>
#include <cstdint>
#include <math.h>

#define SEQ 512
#define BATCH 128
#define INDIM 256
#define HIDDIM 512
#define OUTDIM 256
#define K0 768
#define K1 1024
#define NBLK 256
#define NTHR 256
#define KT 16
#define TF (KT*BATCH)               /* 2048 floats = 8KB */
#define GT0 24                      /* tiles per K-group, layer0 (48 total) */
#define GT1 32                      /* tiles per K-group, layer1 (64 total) */

#define SM_W0_BYTES (K0*2*16)       /* 24576 */
#define SM_W1_BYTES (K1*2*16)       /* 32768 */
#define SM_IN_OFF   (SM_W0_BYTES + SM_W1_BYTES)   /* 57344 */
#define SM_RED_OFF  (SM_IN_OFF + 4*TF*4)          /* 90112 */
#define SM_WOUT_OFF (SM_RED_OFF + 4096)           /* 94208 */
#define SMEM_BYTES  (SM_WOUT_OFF + HIDDIM*4)      /* 96256 -> 2 CTAs/SM */

__device__ float g_xT[(size_t)SEQ*INDIM*BATCH];   /* [t][k][b] */
__device__ float g_h0[2][HIDDIM*BATCH];           /* [phase][j][b] */
__device__ float g_h1[2][HIDDIM*BATCH];
__device__ unsigned g_cnt;
__device__ unsigned g_gen;

typedef unsigned long long ull;

__device__ __forceinline__ ull PK(float x, float y){
    ull r; asm("mov.b64 %0, {%1, %2};" : "=l"(r) : "f"(x), "f"(y)); return r;
}
__device__ __forceinline__ float2 UPK(ull a){
    float2 f; asm("mov.b64 {%0, %1}, %2;" : "=f"(f.x), "=f"(f.y) : "l"(a)); return f;
}
#define FMA2(acc,a,w) asm("fma.rn.f32x2 %0, %1, %2, %0;" : "+l"(acc) : "l"(a), "l"(w))
#define ADD2(acc,b)   asm("add.rn.f32x2 %0, %0, %1;"     : "+l"(acc) : "l"(b))

__device__ __forceinline__ void cpa16(float* dst, const float* src){
    unsigned d = (unsigned)__cvta_generic_to_shared(dst);
    asm volatile("cp.async.cg.shared.global [%0], [%1], 16;" :: "r"(d), "l"(src) : "memory");
}
#define CP_COMMIT() asm volatile("cp.async.commit_group;" ::: "memory")
#define CP_WAIT0()  asm volatile("cp.async.wait_group 0;" ::: "memory")

/* one 8KB tile staged by the 128 threads of one K-group: 2 x 16B each */
__device__ __forceinline__ void stage_tile(float* dst, const float* src, int gtid){
    #pragma unroll
    for (int i = 0; i < 4; i++){
        int off = (i*128 + gtid) * 4;
        cpa16(dst + off, src + off);
    }
    CP_COMMIT();
}

__device__ __forceinline__ float sigf(float x){ return 1.0f/(1.0f+expf(-x)); }

__device__ __forceinline__ void grid_sync(){
    __syncthreads();
    if (threadIdx.x == 0){
        volatile unsigned* vg = &g_gen;
        unsigned gen = *vg;
        __threadfence();
        if (atomicAdd(&g_cnt, 1u) == NBLK-1u){
            atomicExch(&g_cnt, 0u);
            __threadfence();
            atomicAdd(&g_gen, 1u);
        } else {
            while (*vg == gen) { __nanosleep(20); }
        }
        __threadfence();
    }
    __syncthreads();
}

/* x [t][b][k] -> g_xT [t][k][b] */
__global__ void transpose_x(const float* __restrict__ x){
    __shared__ float tile[32][33];
    int t = blockIdx.x, k0 = blockIdx.y*32, b0 = blockIdx.z*32;
    const float* src = x + (size_t)t*BATCH*INDIM;
    #pragma unroll
    for (int i = threadIdx.y; i < 32; i += 8)
        tile[i][threadIdx.x] = src[(size_t)(b0+i)*INDIM + k0 + threadIdx.x];
    __syncthreads();
    float* dst = g_xT + (size_t)t*INDIM*BATCH;
    #pragma unroll
    for (int i = threadIdx.y; i < 32; i += 8)
        dst[(size_t)(k0+i)*BATCH + b0 + threadIdx.x] = tile[threadIdx.x][i];
}

__global__ void __launch_bounds__(NTHR, 2) lstm_persist(
    const float* __restrict__ Wg0, const float* __restrict__ bg0,
    const float* __restrict__ Wg1, const float* __restrict__ bg1,
    const float* __restrict__ W_out, const float* __restrict__ b_out,
    float* __restrict__ out)
{
    extern __shared__ char smem[];
    ulonglong2* wS0  = (ulonglong2*)smem;                 /* [k*2+jl] = {(wf,wi),(wc,wo)} */
    ulonglong2* wS1  = (ulonglong2*)(smem + SM_W0_BYTES);
    float*      inS  = (float*)(smem + SM_IN_OFF);        /* 4 x [KT][BATCH]: grp0 x2, grp1 x2 */
    ulonglong2* redS = (ulonglong2*)(smem + SM_RED_OFF);  /* 128 threads x 2 partial-pairs */
    float*      wOutS= (float*)(smem + SM_WOUT_OFF);      /* W_out column bid, 512 floats */

    const int tid  = threadIdx.x, bid = blockIdx.x;
    const int g    = tid >> 7;          /* K-group 0/1 */
    const int gtid = tid & 127;
    const int jl   = gtid >> 6;         /* local unit 0/1 */
    const int p    = gtid & 63;         /* batch pair: 2p, 2p+1 */
    const int u    = bid*2 + jl;        /* global hidden unit */
    float* bufg = inS + g*2*TF;

    /* ---- weights -> smem, pre-packed gate pairs ---- */
    for (int idx = tid; idx < K0*2; idx += NTHR){
        int k = idx >> 1, uu = bid*2 + (idx & 1);
        float wf = Wg0[(size_t)(0*HIDDIM+uu)*K0 + k];
        float wi = Wg0[(size_t)(1*HIDDIM+uu)*K0 + k];
        float wc = Wg0[(size_t)(2*HIDDIM+uu)*K0 + k];
        float wo = Wg0[(size_t)(3*HIDDIM+uu)*K0 + k];
        wS0[idx] = make_ulonglong2(PK(wf,wi), PK(wc,wo));
    }
    for (int idx = tid; idx < K1*2; idx += NTHR){
        int k = idx >> 1, uu = bid*2 + (idx & 1);
        float wf = Wg1[(size_t)(0*HIDDIM+uu)*K1 + k];
        float wi = Wg1[(size_t)(1*HIDDIM+uu)*K1 + k];
        float wc = Wg1[(size_t)(2*HIDDIM+uu)*K1 + k];
        float wo = Wg1[(size_t)(3*HIDDIM+uu)*K1 + k];
        wS1[idx] = make_ulonglong2(PK(wf,wi), PK(wc,wo));
    }
    for (int j = tid; j < HIDDIM; j += NTHR)
        wOutS[j] = W_out[(size_t)bid*HIDDIM + j];

    const ull b0fi = PK(bg0[u],          bg0[HIDDIM+u]);
    const ull b0co = PK(bg0[2*HIDDIM+u], bg0[3*HIDDIM+u]);
    const ull b1fi = PK(bg1[u],          bg1[HIDDIM+u]);
    const ull b1co = PK(bg1[2*HIDDIM+u], bg1[3*HIDDIM+u]);

    float C0x=0.f,C0y=0.f,C1x=0.f,C1y=0.f;
    float h0x=0.f,h0y=0.f,h1x=0.f,h1y=0.f;

    /* zero this block's h slices, both phases (fresh per replay) */
    if (g == 0){
        float2 z = make_float2(0.f, 0.f);
        int o2 = u*BATCH + 2*p;
        *(float2*)(g_h0[0]+o2) = z; *(float2*)(g_h0[1]+o2) = z;
        *(float2*)(g_h1[0]+o2) = z; *(float2*)(g_h1[1]+o2) = z;
    }
    grid_sync();

    const size_t OB = (size_t)SEQ*BATCH*OUTDIM;

    for (int t = 0; t < SEQ; t++){
        const int cw = t & 1, pv = cw ^ 1;

        /* ================= layer 0 (K split across groups) ================= */
        const float* xb  = g_xT + (size_t)t*INDIM*BATCH;
        const float* h0p = g_h0[pv];
        ull aA,aB,aC,aD;
        if (g == 0){ aA=b0fi; aB=b0co; aC=b0fi; aD=b0co; }
        else       { aA=0;    aB=0;    aC=0;    aD=0;    }

        {
            int gi0 = g*GT0;
            const float* s0 = (gi0 < 16) ? xb + gi0*TF : h0p + (gi0-16)*TF;
            stage_tile(bufg, s0, gtid);
        }
        for (int kt = 0; kt < GT0; kt++){
            CP_WAIT0();
            __syncthreads();
            if (kt+1 < GT0){
                int gi = g*GT0 + kt + 1;
                const float* s = (gi < 16) ? xb + gi*TF : h0p + (gi-16)*TF;
                stage_tile(bufg + ((kt+1)&1)*TF, s, gtid);
            }
            const ulonglong2* wp = wS0 + (g*(K0/2) + kt*KT)*2 + jl;
            const float* ip = bufg + (kt&1)*TF + 2*p;
            #pragma unroll
            for (int kk = 0; kk < KT; kk++){
                float2 v = *(const float2*)(ip + kk*BATCH);
                ulonglong2 w = wp[kk*2];
                ull a0 = PK(v.x, v.x), a1 = PK(v.y, v.y);
                FMA2(aA, a0, w.x); FMA2(aB, a0, w.y);
                FMA2(aC, a1, w.x); FMA2(aD, a1, w.y);
            }
        }
        __syncthreads();
        if (g == 1){
            redS[2*gtid]   = make_ulonglong2(aA, aB);
            redS[2*gtid+1] = make_ulonglong2(aC, aD);
        }
        __syncthreads();
        if (g == 0){
            ulonglong2 r1 = redS[2*gtid], r2 = redS[2*gtid+1];
            ADD2(aA, r1.x); ADD2(aB, r1.y); ADD2(aC, r2.x); ADD2(aD, r2.y);
            float2 fi0=UPK(aA), co0=UPK(aB), fi1=UPK(aC), co1=UPK(aD);
            C0x = sigf(fi0.x)*C0x + sigf(fi0.y)*tanhf(co0.x);
            h0x = sigf(co0.y)*tanhf(C0x);
            C0y = sigf(fi1.x)*C0y + sigf(fi1.y)*tanhf(co1.x);
            h0y = sigf(co1.y)*tanhf(C0y);
            *(float2*)(g_h0[cw] + u*BATCH + 2*p) = make_float2(h0x, h0y);
        }

        grid_sync();   /* the single per-step barrier */

        /* ========= layer 1 (K split) + fused out[t-1] in group1 ========= */
        const float* h0c = g_h0[cw];
        const float* h1p = g_h1[pv];
        if (g == 0){ aA=b1fi; aB=b1co; aC=b1fi; aD=b1co; }
        else       { aA=0;    aB=0;    aC=0;    aD=0;    }
        ull oacc = 0;

        {
            int gi0 = g*GT1;
            const float* s0 = (gi0 < 32) ? h0c + gi0*TF : h1p + (gi0-32)*TF;
            stage_tile(bufg, s0, gtid);
        }
        for (int kt = 0; kt < GT1; kt++){
            CP_WAIT0();
            __syncthreads();
            if (kt+1 < GT1){
                int gi = g*GT1 + kt + 1;
                const float* s = (gi < 32) ? h0c + gi*TF : h1p + (gi-32)*TF;
                stage_tile(bufg + ((kt+1)&1)*TF, s, gtid);
            }
            const ulonglong2* wp = wS1 + (g*(K1/2) + kt*KT)*2 + jl;
            const float* ip = bufg + (kt&1)*TF + 2*p;
            #pragma unroll
            for (int kk = 0; kk < KT; kk++){
                float2 v = *(const float2*)(ip + kk*BATCH);
                ulonglong2 w = wp[kk*2];
                ull a0 = PK(v.x, v.x), a1 = PK(v.y, v.y);
                FMA2(aA, a0, w.x); FMA2(aB, a0, w.y);
                FMA2(aC, a1, w.x); FMA2(aD, a1, w.y);
            }
            /* out[t-1] rides group1's h1[t-1] tiles (j0 = kt*KT); col = bid */
            if (g == 1 && t > 0 && jl == 0){
                const float* wob = wOutS + kt*KT;
                const float* ip2 = bufg + (kt&1)*TF + 2*p;
                #pragma unroll
                for (int kk = 0; kk < KT; kk++){
                    float2 v = *(const float2*)(ip2 + kk*BATCH);
                    float w = wob[kk];
                    FMA2(oacc, PK(v.x, v.y), PK(w, w));
                }
            }
        }
        __syncthreads();
        if (g == 1){
            redS[2*gtid]   = make_ulonglong2(aA, aB);
            redS[2*gtid+1] = make_ulonglong2(aC, aD);
        }
        __syncthreads();
        if (g == 0){
            ulonglong2 r1 = redS[2*gtid], r2 = redS[2*gtid+1];
            ADD2(aA, r1.x); ADD2(aB, r1.y); ADD2(aC, r2.x); ADD2(aD, r2.y);
            float2 fi0=UPK(aA), co0=UPK(aB), fi1=UPK(aC), co1=UPK(aD);
            C1x = sigf(fi0.x)*C1x + sigf(fi0.y)*tanhf(co0.x);
            h1x = sigf(co0.y)*tanhf(C1x);
            C1y = sigf(fi1.x)*C1y + sigf(fi1.y)*tanhf(co1.x);
            h1y = sigf(co1.y)*tanhf(C1y);
            *(float2*)(g_h1[cw] + u*BATCH + 2*p) = make_float2(h1x, h1y);
        }
        if (g == 1 && t > 0 && jl == 0){
            float2 ov = UPK(oacc);
            float bo = b_out[bid];
            size_t ob = ((size_t)(t-1)*BATCH + 2*p)*OUTDIM + bid;
            out[ob]          = ov.x + bo;
            out[ob + OUTDIM] = ov.y + bo;
        }
    }

    grid_sync();
    /* out[SEQ-1]: 64 threads, column bid */
    if (tid < 64){
        ull oacc = 0;
        const float* h1f = g_h1[(SEQ-1)&1];
        #pragma unroll 4
        for (int j = 0; j < HIDDIM; j++){
            float2 v = __ldcg((const float2*)(h1f + j*BATCH + 2*tid));
            float w = wOutS[j];
            FMA2(oacc, PK(v.x, v.y), PK(w, w));
        }
        float2 ov = UPK(oacc);
        float bo = b_out[bid];
        size_t ob = ((size_t)(SEQ-1)*BATCH + 2*tid)*OUTDIM + bid;
        out[ob]          = ov.x + bo;
        out[ob + OUTDIM] = ov.y + bo;
    }
    /* final states: [B][HID] each, order h_0, C_0, h_1, C_1 (group0 holds them) */
    if (g == 0){
        size_t r0 = (size_t)(2*p)*HIDDIM + u;
        size_t r1 = (size_t)(2*p+1)*HIDDIM + u;
        out[OB          + r0] = h0x;  out[OB          + r1] = h0y;
        out[OB +  65536 + r0] = C0x;  out[OB +  65536 + r1] = C0y;
        out[OB + 131072 + r0] = h1x;  out[OB + 131072 + r1] = h1y;
        out[OB + 196608 + r0] = C1x;  out[OB + 196608 + r1] = C1y;
    }
}

extern "C" void kernel_launch(void* const* d_in, const int* in_sizes, int n_in,
                              void* d_out, int out_size)
{
    (void)in_sizes; (void)n_in; (void)out_size;
    const float* x     = (const float*)d_in[0];
    const float* Wg0   = (const float*)d_in[1];
    const float* bg0   = (const float*)d_in[2];
    const float* Wg1   = (const float*)d_in[3];
    const float* bg1   = (const float*)d_in[4];
    const float* W_out = (const float*)d_in[5];
    const float* b_out = (const float*)d_in[6];

    cudaFuncSetAttribute(lstm_persist,
                         cudaFuncAttributeMaxDynamicSharedMemorySize, SMEM_BYTES);

    transpose_x<<<dim3(SEQ, INDIM/32, BATCH/32), dim3(32, 8)>>>(x);
    lstm_persist<<<NBLK, NTHR, SMEM_BYTES>>>(Wg0, bg0, Wg1, bg1, W_out, b_out,
                                             (float*)d_out);
}

// round 9
// speedup vs baseline: 1.3403x; 1.1550x over previous
#include <cuda_runtime.h>
#include <cstdint>
#include <math.h>

#define SEQ 512
#define BATCH 128
#define INDIM 256
#define HIDDIM 512
#define OUTDIM 256
#define K0 768
#define K1 1024
#define NBLK 256
#define NTHR 256
#define KT 8
#define TF (KT*BATCH)               /* 1024 floats = 4KB */
#define GT0 24                      /* tiles per K-group, layer0 (96 total) */
#define GT1 32                      /* tiles per K-group, layer1 (128 total) */

#define SM_W0_BYTES (K0*2*16)       /* 24576 */
#define SM_W1_BYTES (K1*2*16)       /* 32768 */
#define SM_IN_OFF   (SM_W0_BYTES + SM_W1_BYTES)   /* 57344 */
#define SM_RED_OFF  (SM_IN_OFF + 8*TF*4)          /* 90112: 4 groups x 2 bufs */
#define SM_OACC_OFF (SM_RED_OFF + 3*64*64)        /* 102400 */
#define SM_WOUT_OFF (SM_OACC_OFF + 2*64*8)        /* 103424 */
#define SMEM_BYTES  (SM_WOUT_OFF + HIDDIM*4)      /* 105472 -> 2 CTAs/SM */

__device__ float g_xT[(size_t)SEQ*INDIM*BATCH];   /* [t][k][b] */
__device__ float g_h0[2][HIDDIM*BATCH];           /* [phase][j][b] */
__device__ float g_h1[2][HIDDIM*BATCH];
__device__ unsigned g_cnt;
__device__ unsigned g_gen;

typedef unsigned long long ull;

__device__ __forceinline__ ull PK(float x, float y){
    ull r; asm("mov.b64 %0, {%1, %2};" : "=l"(r) : "f"(x), "f"(y)); return r;
}
__device__ __forceinline__ float2 UPK(ull a){
    float2 f; asm("mov.b64 {%0, %1}, %2;" : "=f"(f.x), "=f"(f.y) : "l"(a)); return f;
}
#define FMA2(acc,a,w) asm("fma.rn.f32x2 %0, %1, %2, %0;" : "+l"(acc) : "l"(a), "l"(w))
#define ADD2(acc,b)   asm("add.rn.f32x2 %0, %0, %1;"     : "+l"(acc) : "l"(b))

__device__ __forceinline__ void cpa16(float* dst, const float* src){
    unsigned d = (unsigned)__cvta_generic_to_shared(dst);
    asm volatile("cp.async.cg.shared.global [%0], [%1], 16;" :: "r"(d), "l"(src) : "memory");
}
#define CP_COMMIT() asm volatile("cp.async.commit_group;" ::: "memory")
#define CP_WAIT0()  asm volatile("cp.async.wait_group 0;" ::: "memory")

/* one 4KB tile staged by the 64 threads of one K-group: 1 x 16B x 4 */
__device__ __forceinline__ void stage_tile(float* dst, const float* src, int p){
    #pragma unroll
    for (int i = 0; i < 4; i++){
        int off = (i*64 + p) * 4;
        cpa16(dst + off, src + off);
    }
    CP_COMMIT();
}

__device__ __forceinline__ float sigf(float x){ return 1.0f/(1.0f+expf(-x)); }

__device__ __forceinline__ void grid_sync(){
    __syncthreads();
    if (threadIdx.x == 0){
        volatile unsigned* vg = &g_gen;
        unsigned gen = *vg;
        __threadfence();
        if (atomicAdd(&g_cnt, 1u) == NBLK-1u){
            atomicExch(&g_cnt, 0u);
            __threadfence();
            atomicAdd(&g_gen, 1u);
        } else {
            while (*vg == gen) { __nanosleep(20); }
        }
        __threadfence();
    }
    __syncthreads();
}

/* x [t][b][k] -> g_xT [t][k][b] */
__global__ void transpose_x(const float* __restrict__ x){
    __shared__ float tile[32][33];
    int t = blockIdx.x, k0 = blockIdx.y*32, b0 = blockIdx.z*32;
    const float* src = x + (size_t)t*BATCH*INDIM;
    #pragma unroll
    for (int i = threadIdx.y; i < 32; i += 8)
        tile[i][threadIdx.x] = src[(size_t)(b0+i)*INDIM + k0 + threadIdx.x];
    __syncthreads();
    float* dst = g_xT + (size_t)t*INDIM*BATCH;
    #pragma unroll
    for (int i = threadIdx.y; i < 32; i += 8)
        dst[(size_t)(k0+i)*BATCH + b0 + threadIdx.x] = tile[threadIdx.x][i];
}

__global__ void __launch_bounds__(NTHR, 2) lstm_persist(
    const float* __restrict__ Wg0, const float* __restrict__ bg0,
    const float* __restrict__ Wg1, const float* __restrict__ bg1,
    const float* __restrict__ W_out, const float* __restrict__ b_out,
    float* __restrict__ out)
{
    extern __shared__ char smem[];
    ulonglong2* wS0  = (ulonglong2*)smem;                 /* [k*2+unit] = {(wf,wi),(wc,wo)} */
    ulonglong2* wS1  = (ulonglong2*)(smem + SM_W0_BYTES);
    float*      inS  = (float*)(smem + SM_IN_OFF);        /* 4 groups x 2 x [KT][BATCH] */
    ulonglong2* redS = (ulonglong2*)(smem + SM_RED_OFF);  /* 3 groups x 64 thr x 4 */
    ull*        oaccS= (ull*)(smem + SM_OACC_OFF);        /* 2 x 64 */
    float*      wOutS= (float*)(smem + SM_WOUT_OFF);      /* W_out row bid, 512 floats */

    const int tid = threadIdx.x, bid = blockIdx.x;
    const int g   = tid >> 6;           /* K-group 0..3 */
    const int p   = tid & 63;           /* batch pair: 2p, 2p+1 */
    const int u0  = bid*2, u1 = bid*2 + 1;
    float* bufg = inS + g*2*TF;

    /* ---- weights -> smem, pre-packed gate pairs ---- */
    for (int idx = tid; idx < K0*2; idx += NTHR){
        int k = idx >> 1, uu = bid*2 + (idx & 1);
        float wf = Wg0[(size_t)(0*HIDDIM+uu)*K0 + k];
        float wi = Wg0[(size_t)(1*HIDDIM+uu)*K0 + k];
        float wc = Wg0[(size_t)(2*HIDDIM+uu)*K0 + k];
        float wo = Wg0[(size_t)(3*HIDDIM+uu)*K0 + k];
        wS0[idx] = make_ulonglong2(PK(wf,wi), PK(wc,wo));
    }
    for (int idx = tid; idx < K1*2; idx += NTHR){
        int k = idx >> 1, uu = bid*2 + (idx & 1);
        float wf = Wg1[(size_t)(0*HIDDIM+uu)*K1 + k];
        float wi = Wg1[(size_t)(1*HIDDIM+uu)*K1 + k];
        float wc = Wg1[(size_t)(2*HIDDIM+uu)*K1 + k];
        float wo = Wg1[(size_t)(3*HIDDIM+uu)*K1 + k];
        wS1[idx] = make_ulonglong2(PK(wf,wi), PK(wc,wo));
    }
    for (int j = tid; j < HIDDIM; j += NTHR)
        wOutS[j] = W_out[(size_t)bid*HIDDIM + j];

    const ull b0fiU0 = PK(bg0[u0], bg0[HIDDIM+u0]);
    const ull b0coU0 = PK(bg0[2*HIDDIM+u0], bg0[3*HIDDIM+u0]);
    const ull b0fiU1 = PK(bg0[u1], bg0[HIDDIM+u1]);
    const ull b0coU1 = PK(bg0[2*HIDDIM+u1], bg0[3*HIDDIM+u1]);
    const ull b1fiU0 = PK(bg1[u0], bg1[HIDDIM+u0]);
    const ull b1coU0 = PK(bg1[2*HIDDIM+u0], bg1[3*HIDDIM+u0]);
    const ull b1fiU1 = PK(bg1[u1], bg1[HIDDIM+u1]);
    const ull b1coU1 = PK(bg1[2*HIDDIM+u1], bg1[3*HIDDIM+u1]);

    /* cell/hidden state (live in group 0 only) */
    float c0u0x=0.f,c0u0y=0.f,c0u1x=0.f,c0u1y=0.f;
    float c1u0x=0.f,c1u0y=0.f,c1u1x=0.f,c1u1y=0.f;
    float h0u0x=0.f,h0u0y=0.f,h0u1x=0.f,h0u1y=0.f;
    float h1u0x=0.f,h1u0y=0.f,h1u1x=0.f,h1u1y=0.f;

    /* zero this block's h slices, both phases (fresh per replay) */
    if (g == 0){
        float2 z = make_float2(0.f, 0.f);
        *(float2*)(g_h0[0]+u0*BATCH+2*p) = z; *(float2*)(g_h0[1]+u0*BATCH+2*p) = z;
        *(float2*)(g_h0[0]+u1*BATCH+2*p) = z; *(float2*)(g_h0[1]+u1*BATCH+2*p) = z;
        *(float2*)(g_h1[0]+u0*BATCH+2*p) = z; *(float2*)(g_h1[1]+u0*BATCH+2*p) = z;
        *(float2*)(g_h1[0]+u1*BATCH+2*p) = z; *(float2*)(g_h1[1]+u1*BATCH+2*p) = z;
    }
    grid_sync();

    const size_t OB = (size_t)SEQ*BATCH*OUTDIM;

    for (int t = 0; t < SEQ; t++){
        const int cw = t & 1, pv = cw ^ 1;

        /* ================= layer 0 (K split 4 ways) ================= */
        const float* xb  = g_xT + (size_t)t*INDIM*BATCH;
        const float* h0p = g_h0[pv];
        ull A0,B0,C0,D0,A1,B1,C1,D1;
        if (g == 0){ A0=b0fiU0; B0=b0coU0; C0=b0fiU0; D0=b0coU0;
                     A1=b0fiU1; B1=b0coU1; C1=b0fiU1; D1=b0coU1; }
        else       { A0=B0=C0=D0=A1=B1=C1=D1=0; }

        {
            int gi0 = g*GT0;
            const float* s0 = (gi0 < 32) ? xb + gi0*TF : h0p + (gi0-32)*TF;
            stage_tile(bufg, s0, p);
        }
        for (int kt = 0; kt < GT0; kt++){
            CP_WAIT0();
            __syncthreads();
            if (kt+1 < GT0){
                int gi = g*GT0 + kt + 1;
                const float* s = (gi < 32) ? xb + gi*TF : h0p + (gi-32)*TF;
                stage_tile(bufg + ((kt+1)&1)*TF, s, p);
            }
            const ulonglong2* wp = wS0 + (g*(K0/4) + kt*KT)*2;
            const float* ip = bufg + (kt&1)*TF + 2*p;
            #pragma unroll
            for (int kk = 0; kk < KT; kk++){
                float2 v = *(const float2*)(ip + kk*BATCH);
                ulonglong2 w0 = wp[kk*2], w1 = wp[kk*2+1];
                ull a0 = PK(v.x, v.x), a1 = PK(v.y, v.y);
                FMA2(A0, a0, w0.x); FMA2(B0, a0, w0.y);
                FMA2(C0, a1, w0.x); FMA2(D0, a1, w0.y);
                FMA2(A1, a0, w1.x); FMA2(B1, a0, w1.y);
                FMA2(C1, a1, w1.x); FMA2(D1, a1, w1.y);
            }
        }
        __syncthreads();
        if (g > 0){
            ulonglong2* r = redS + ((g-1)*64 + p)*4;
            r[0] = make_ulonglong2(A0, B0); r[1] = make_ulonglong2(C0, D0);
            r[2] = make_ulonglong2(A1, B1); r[3] = make_ulonglong2(C1, D1);
        }
        __syncthreads();
        if (g == 0){
            #pragma unroll
            for (int gg = 0; gg < 3; gg++){
                const ulonglong2* r = redS + (gg*64 + p)*4;
                ulonglong2 r0=r[0], r1=r[1], r2=r[2], r3=r[3];
                ADD2(A0, r0.x); ADD2(B0, r0.y); ADD2(C0, r1.x); ADD2(D0, r1.y);
                ADD2(A1, r2.x); ADD2(B1, r2.y); ADD2(C1, r3.x); ADD2(D1, r3.y);
            }
            float2 fx, cx;
            fx=UPK(A0); cx=UPK(B0);
            c0u0x = sigf(fx.x)*c0u0x + sigf(fx.y)*tanhf(cx.x);
            h0u0x = sigf(cx.y)*tanhf(c0u0x);
            fx=UPK(C0); cx=UPK(D0);
            c0u0y = sigf(fx.x)*c0u0y + sigf(fx.y)*tanhf(cx.x);
            h0u0y = sigf(cx.y)*tanhf(c0u0y);
            fx=UPK(A1); cx=UPK(B1);
            c0u1x = sigf(fx.x)*c0u1x + sigf(fx.y)*tanhf(cx.x);
            h0u1x = sigf(cx.y)*tanhf(c0u1x);
            fx=UPK(C1); cx=UPK(D1);
            c0u1y = sigf(fx.x)*c0u1y + sigf(fx.y)*tanhf(cx.x);
            h0u1y = sigf(cx.y)*tanhf(c0u1y);
            *(float2*)(g_h0[cw] + u0*BATCH + 2*p) = make_float2(h0u0x, h0u0y);
            *(float2*)(g_h0[cw] + u1*BATCH + 2*p) = make_float2(h0u1x, h0u1y);
        }

        grid_sync();   /* the single per-step barrier */

        /* ========= layer 1 (K split 4 ways) + fused out[t-1] ========= */
        const float* h0c = g_h0[cw];
        const float* h1p = g_h1[pv];
        if (g == 0){ A0=b1fiU0; B0=b1coU0; C0=b1fiU0; D0=b1coU0;
                     A1=b1fiU1; B1=b1coU1; C1=b1fiU1; D1=b1coU1; }
        else       { A0=B0=C0=D0=A1=B1=C1=D1=0; }
        ull oacc = 0;

        {
            int gi0 = g*GT1;
            const float* s0 = (gi0 < 64) ? h0c + gi0*TF : h1p + (gi0-64)*TF;
            stage_tile(bufg, s0, p);
        }
        for (int kt = 0; kt < GT1; kt++){
            CP_WAIT0();
            __syncthreads();
            if (kt+1 < GT1){
                int gi = g*GT1 + kt + 1;
                const float* s = (gi < 64) ? h0c + gi*TF : h1p + (gi-64)*TF;
                stage_tile(bufg + ((kt+1)&1)*TF, s, p);
            }
            const ulonglong2* wp = wS1 + (g*(K1/4) + kt*KT)*2;
            const float* ip = bufg + (kt&1)*TF + 2*p;
            #pragma unroll
            for (int kk = 0; kk < KT; kk++){
                float2 v = *(const float2*)(ip + kk*BATCH);
                ulonglong2 w0 = wp[kk*2], w1 = wp[kk*2+1];
                ull a0 = PK(v.x, v.x), a1 = PK(v.y, v.y);
                FMA2(A0, a0, w0.x); FMA2(B0, a0, w0.y);
                FMA2(C0, a1, w0.x); FMA2(D0, a1, w0.y);
                FMA2(A1, a0, w1.x); FMA2(B1, a0, w1.y);
                FMA2(C1, a1, w1.x); FMA2(D1, a1, w1.y);
            }
            /* out[t-1]: groups 2,3 own the h1[t-1] K-range (gi>=64) */
            if (g >= 2 && t > 0){
                const float* wob = wOutS + (g-2)*(K1/4) + kt*KT;
                const float* ip2 = bufg + (kt&1)*TF + 2*p;
                #pragma unroll
                for (int kk = 0; kk < KT; kk++){
                    float2 v = *(const float2*)(ip2 + kk*BATCH);
                    float w = wob[kk];
                    FMA2(oacc, PK(v.x, v.y), PK(w, w));
                }
            }
        }
        __syncthreads();
        if (g > 0){
            ulonglong2* r = redS + ((g-1)*64 + p)*4;
            r[0] = make_ulonglong2(A0, B0); r[1] = make_ulonglong2(C0, D0);
            r[2] = make_ulonglong2(A1, B1); r[3] = make_ulonglong2(C1, D1);
        }
        if (g >= 2) oaccS[(g-2)*64 + p] = oacc;
        __syncthreads();
        if (g == 0){
            #pragma unroll
            for (int gg = 0; gg < 3; gg++){
                const ulonglong2* r = redS + (gg*64 + p)*4;
                ulonglong2 r0=r[0], r1=r[1], r2=r[2], r3=r[3];
                ADD2(A0, r0.x); ADD2(B0, r0.y); ADD2(C0, r1.x); ADD2(D0, r1.y);
                ADD2(A1, r2.x); ADD2(B1, r2.y); ADD2(C1, r3.x); ADD2(D1, r3.y);
            }
            float2 fx, cx;
            fx=UPK(A0); cx=UPK(B0);
            c1u0x = sigf(fx.x)*c1u0x + sigf(fx.y)*tanhf(cx.x);
            h1u0x = sigf(cx.y)*tanhf(c1u0x);
            fx=UPK(C0); cx=UPK(D0);
            c1u0y = sigf(fx.x)*c1u0y + sigf(fx.y)*tanhf(cx.x);
            h1u0y = sigf(cx.y)*tanhf(c1u0y);
            fx=UPK(A1); cx=UPK(B1);
            c1u1x = sigf(fx.x)*c1u1x + sigf(fx.y)*tanhf(cx.x);
            h1u1x = sigf(cx.y)*tanhf(c1u1x);
            fx=UPK(C1); cx=UPK(D1);
            c1u1y = sigf(fx.x)*c1u1y + sigf(fx.y)*tanhf(cx.x);
            h1u1y = sigf(cx.y)*tanhf(c1u1y);
            *(float2*)(g_h1[cw] + u0*BATCH + 2*p) = make_float2(h1u0x, h1u0y);
            *(float2*)(g_h1[cw] + u1*BATCH + 2*p) = make_float2(h1u1x, h1u1y);
        }
        if (g == 1 && t > 0){
            ull o = oaccS[p];
            ADD2(o, oaccS[64 + p]);
            float2 ov = UPK(o);
            float bo = b_out[bid];
            size_t ob = ((size_t)(t-1)*BATCH + 2*p)*OUTDIM + bid;
            out[ob]          = ov.x + bo;
            out[ob + OUTDIM] = ov.y + bo;
        }
    }

    grid_sync();
    /* out[SEQ-1]: 64 threads, column bid */
    if (tid < 64){
        ull oacc = 0;
        const float* h1f = g_h1[(SEQ-1)&1];
        #pragma unroll 4
        for (int j = 0; j < HIDDIM; j++){
            float2 v = __ldcg((const float2*)(h1f + j*BATCH + 2*tid));
            float w = wOutS[j];
            FMA2(oacc, PK(v.x, v.y), PK(w, w));
        }
        float2 ov = UPK(oacc);
        float bo = b_out[bid];
        size_t ob = ((size_t)(SEQ-1)*BATCH + 2*tid)*OUTDIM + bid;
        out[ob]          = ov.x + bo;
        out[ob + OUTDIM] = ov.y + bo;
    }
    /* final states: [B][HID] each, order h_0, C_0, h_1, C_1 (group0 holds them) */
    if (g == 0){
        size_t r0 = (size_t)(2*p)*HIDDIM;
        size_t r1 = (size_t)(2*p+1)*HIDDIM;
        out[OB          + r0 + u0] = h0u0x;  out[OB          + r1 + u0] = h0u0y;
        out[OB          + r0 + u1] = h0u1x;  out[OB          + r1 + u1] = h0u1y;
        out[OB +  65536 + r0 + u0] = c0u0x;  out[OB +  65536 + r1 + u0] = c0u0y;
        out[OB +  65536 + r0 + u1] = c0u1x;  out[OB +  65536 + r1 + u1] = c0u1y;
        out[OB + 131072 + r0 + u0] = h1u0x;  out[OB + 131072 + r1 + u0] = h1u0y;
        out[OB + 131072 + r0 + u1] = h1u1x;  out[OB + 131072 + r1 + u1] = h1u1y;
        out[OB + 196608 + r0 + u0] = c1u0x;  out[OB + 196608 + r1 + u0] = c1u0y;
        out[OB + 196608 + r0 + u1] = c1u1x;  out[OB + 196608 + r1 + u1] = c1u1y;
    }
}

extern "C" void kernel_launch(void* const* d_in, const int* in_sizes, int n_in,
                              void* d_out, int out_size)
{
    (void)in_sizes; (void)n_in; (void)out_size;
    const float* x     = (const float*)d_in[0];
    const float* Wg0   = (const float*)d_in[1];
    const float* bg0   = (const float*)d_in[2];
    const float* Wg1   = (const float*)d_in[3];
    const float* bg1   = (const float*)d_in[4];
    const float* W_out = (const float*)d_in[5];
    const float* b_out = (const float*)d_in[6];

    cudaFuncSetAttribute(lstm_persist,
                         cudaFuncAttributeMaxDynamicSharedMemorySize, SMEM_BYTES);

    transpose_x<<<dim3(SEQ, INDIM/32, BATCH/32), dim3(32, 8)>>>(x);
    lstm_persist<<<NBLK, NTHR, SMEM_BYTES>>>(Wg0, bg0, Wg1, bg1, W_out, b_out,
                                             (float*)d_out);
}

// round 10
// speedup vs baseline: 1.4650x; 1.0930x over previous
#include <cuda_runtime.h>
#include <cstdint>
#include <math.h>

#define SEQ 512
#define BATCH 128
#define INDIM 256
#define HIDDIM 512
#define OUTDIM 256
#define K0 768
#define K1 1024
#define NBLK 128
#define NTHR 512
#define KT 4
#define TF (KT*BATCH)               /* 512 floats = 2KB */
#define GT0 24                      /* tiles per group, layer0 (192 total) */
#define GT1 32                      /* tiles per group, layer1 (256 total) */

#define SM_W0   0
#define SM_W1   (SM_W0 + K0*4*16)            /* 49152 */
#define SM_IN   (SM_W1 + K1*4*16)            /* 114688 */
#define SM_RED  (SM_IN + 8*2*TF*4)           /* 147456 */
#define SM_OACC (SM_RED + 8*448*16)          /* 204800 */
#define SM_WOUT (SM_OACC + 4*64*16)          /* 208896 */
#define SM_CS   (SM_WOUT + 1024*8)           /* 217088 */
#define SM_BS   (SM_CS + 1024*4)             /* 221184 */
#define SMEM_BYTES (SM_BS + 128)             /* 221312 */

__device__ float g_xT[(size_t)SEQ*INDIM*BATCH];   /* [t][k][b] */
__device__ float g_h0[2][HIDDIM*BATCH];           /* [phase][j][b] */
__device__ float g_h1[2][HIDDIM*BATCH];
__device__ unsigned g_cnt;
__device__ unsigned g_gen;

typedef unsigned long long ull;

__device__ __forceinline__ ull PK(float x, float y){
    ull r; asm("mov.b64 %0, {%1, %2};" : "=l"(r) : "f"(x), "f"(y)); return r;
}
__device__ __forceinline__ float2 UPK(ull a){
    float2 f; asm("mov.b64 {%0, %1}, %2;" : "=f"(f.x), "=f"(f.y) : "l"(a)); return f;
}
#define FMA2(acc,a,w) asm("fma.rn.f32x2 %0, %1, %2, %0;" : "+l"(acc) : "l"(a), "l"(w))
#define ADD2(acc,b)   asm("add.rn.f32x2 %0, %0, %1;"     : "+l"(acc) : "l"(b))

__device__ __forceinline__ void cpa16(float* dst, const float* src){
    unsigned d = (unsigned)__cvta_generic_to_shared(dst);
    asm volatile("cp.async.cg.shared.global [%0], [%1], 16;" :: "r"(d), "l"(src) : "memory");
}
#define CP_COMMIT() asm volatile("cp.async.commit_group;" ::: "memory")
#define CP_WAIT0()  asm volatile("cp.async.wait_group 0;" ::: "memory")
#define GBAR(id)    asm volatile("bar.sync %0, %1;" :: "r"(id), "r"(64) : "memory")

/* one 2KB tile staged by the 64 threads of one K-group: 2 x 16B each */
__device__ __forceinline__ void stage_tile(float* dst, const float* src, int p){
    cpa16(dst + p*4,       src + p*4);
    cpa16(dst + 256 + p*4, src + 256 + p*4);
    CP_COMMIT();
}

__device__ __forceinline__ float sigf(float x){ return 1.0f/(1.0f+expf(-x)); }

__device__ __forceinline__ void grid_sync(){
    __syncthreads();
    if (threadIdx.x == 0){
        volatile unsigned* vg = &g_gen;
        unsigned gen = *vg;
        __threadfence();
        if (atomicAdd(&g_cnt, 1u) == NBLK-1u){
            atomicExch(&g_cnt, 0u);
            __threadfence();
            atomicAdd(&g_gen, 1u);
        } else {
            while (*vg == gen) { __nanosleep(20); }
        }
        __threadfence();
    }
    __syncthreads();
}

/* x [t][b][k] -> g_xT [t][k][b] */
__global__ void transpose_x(const float* __restrict__ x){
    __shared__ float tile[32][33];
    int t = blockIdx.x, k0 = blockIdx.y*32, b0 = blockIdx.z*32;
    const float* src = x + (size_t)t*BATCH*INDIM;
    #pragma unroll
    for (int i = threadIdx.y; i < 32; i += 8)
        tile[i][threadIdx.x] = src[(size_t)(b0+i)*INDIM + k0 + threadIdx.x];
    __syncthreads();
    float* dst = g_xT + (size_t)t*INDIM*BATCH;
    #pragma unroll
    for (int i = threadIdx.y; i < 32; i += 8)
        dst[(size_t)(k0+i)*BATCH + b0 + threadIdx.x] = tile[threadIdx.x][i];
}

__global__ void __launch_bounds__(NTHR, 1) lstm_persist(
    const float* __restrict__ Wg0, const float* __restrict__ bg0,
    const float* __restrict__ Wg1, const float* __restrict__ bg1,
    const float* __restrict__ W_out, const float* __restrict__ b_out,
    float* __restrict__ out)
{
    extern __shared__ char smem[];
    ulonglong2* wS0  = (ulonglong2*)(smem + SM_W0);   /* [k*4+u] = {(wf,wi),(wc,wo)} */
    ulonglong2* wS1  = (ulonglong2*)(smem + SM_W1);
    float*      inS  = (float*)(smem + SM_IN);        /* 8 groups x 2 x [KT][BATCH] */
    ulonglong2* redS = (ulonglong2*)(smem + SM_RED);  /* [j<8][(g-1)*64+p], slot-major */
    ulonglong2* oaccS= (ulonglong2*)(smem + SM_OACC); /* [(g-4)*64+p] = (o0,o1) */
    ull*        wOutS= (ull*)(smem + SM_WOUT);        /* [c*512+j] = (w,w) dup */
    float*      cS   = (float*)(smem + SM_CS);        /* [layer*512 + u*128 + b] */
    ulonglong2* bS   = (ulonglong2*)(smem + SM_BS);   /* [layer*4+u] = (bfi,bco) */

    const int tid = threadIdx.x, bid = blockIdx.x;
    const int g   = tid >> 6;           /* K-group 0..7 */
    const int p   = tid & 63;           /* batch pair: 2p, 2p+1 */
    float* bufg = inS + g*2*TF;

    /* ---- weights / consts -> smem ---- */
    for (int idx = tid; idx < K0*4; idx += NTHR){
        int k = idx >> 2, uu = bid*4 + (idx & 3);
        float wf = Wg0[(size_t)(0*HIDDIM+uu)*K0 + k];
        float wi = Wg0[(size_t)(1*HIDDIM+uu)*K0 + k];
        float wc = Wg0[(size_t)(2*HIDDIM+uu)*K0 + k];
        float wo = Wg0[(size_t)(3*HIDDIM+uu)*K0 + k];
        wS0[idx] = make_ulonglong2(PK(wf,wi), PK(wc,wo));
    }
    for (int idx = tid; idx < K1*4; idx += NTHR){
        int k = idx >> 2, uu = bid*4 + (idx & 3);
        float wf = Wg1[(size_t)(0*HIDDIM+uu)*K1 + k];
        float wi = Wg1[(size_t)(1*HIDDIM+uu)*K1 + k];
        float wc = Wg1[(size_t)(2*HIDDIM+uu)*K1 + k];
        float wo = Wg1[(size_t)(3*HIDDIM+uu)*K1 + k];
        wS1[idx] = make_ulonglong2(PK(wf,wi), PK(wc,wo));
    }
    for (int idx = tid; idx < 2*HIDDIM; idx += NTHR){
        int c = idx >> 9, j = idx & 511;
        float w = W_out[(size_t)(bid*2+c)*HIDDIM + j];
        wOutS[idx] = PK(w, w);
    }
    if (tid < 8){
        int L = tid >> 2, u = tid & 3, ug = bid*4 + u;
        const float* bg = L ? bg1 : bg0;
        bS[tid] = make_ulonglong2(PK(bg[ug], bg[HIDDIM+ug]),
                                  PK(bg[2*HIDDIM+ug], bg[3*HIDDIM+ug]));
    }
    for (int idx = tid; idx < 1024; idx += NTHR) cS[idx] = 0.f;
    if (g == 0){
        float2 z = make_float2(0.f, 0.f);
        #pragma unroll
        for (int u = 0; u < 4; u++){
            int o2 = (bid*4+u)*BATCH + 2*p;
            *(float2*)(g_h0[0]+o2) = z; *(float2*)(g_h0[1]+o2) = z;
            *(float2*)(g_h1[0]+o2) = z; *(float2*)(g_h1[1]+o2) = z;
        }
    }
    grid_sync();

    const size_t OB = (size_t)SEQ*BATCH*OUTDIM;

    for (int t = 0; t < SEQ; t++){
        const int cw = t & 1, pv = cw ^ 1;

        /* ================= layer 0 (K split 8 ways) ================= */
        const float* xb  = g_xT + (size_t)t*INDIM*BATCH;
        const float* h0p = g_h0[pv];
        ull A[4]={0,0,0,0}, B[4]={0,0,0,0}, C[4]={0,0,0,0}, D[4]={0,0,0,0};

        {
            int gi0 = g*GT0;
            const float* s0 = (gi0 < 64) ? xb + gi0*TF : h0p + (gi0-64)*TF;
            stage_tile(bufg, s0, p);
        }
        for (int kt = 0; kt < GT0; kt++){
            CP_WAIT0();
            GBAR(1+g);
            if (kt+1 < GT0){
                int gi = g*GT0 + kt + 1;
                const float* s = (gi < 64) ? xb + gi*TF : h0p + (gi-64)*TF;
                stage_tile(bufg + ((kt+1)&1)*TF, s, p);
            }
            const ulonglong2* wp = wS0 + (g*(K0/8) + kt*KT)*4;
            const float* ip = bufg + (kt&1)*TF + 2*p;
            #pragma unroll
            for (int kk = 0; kk < KT; kk++){
                float2 v = *(const float2*)(ip + kk*BATCH);
                ull a0 = PK(v.x, v.x), a1 = PK(v.y, v.y);
                #pragma unroll
                for (int u = 0; u < 4; u++){
                    ulonglong2 w = wp[kk*4 + u];
                    FMA2(A[u], a0, w.x); FMA2(B[u], a0, w.y);
                    FMA2(C[u], a1, w.x); FMA2(D[u], a1, w.y);
                }
            }
        }
        __syncthreads();
        if (g > 0){
            int base = (g-1)*64 + p;
            #pragma unroll
            for (int u = 0; u < 4; u++){
                redS[(2*u)*448   + base] = make_ulonglong2(A[u], B[u]);
                redS[(2*u+1)*448 + base] = make_ulonglong2(C[u], D[u]);
            }
        }
        __syncthreads();
        if (g == 0){
            #pragma unroll 1
            for (int s = 0; s < 7; s++){
                int base = s*64 + p;
                #pragma unroll
                for (int u = 0; u < 4; u++){
                    ulonglong2 r0 = redS[(2*u)*448   + base];
                    ulonglong2 r1 = redS[(2*u+1)*448 + base];
                    ADD2(A[u], r0.x); ADD2(B[u], r0.y);
                    ADD2(C[u], r1.x); ADD2(D[u], r1.y);
                }
            }
            #pragma unroll
            for (int u = 0; u < 4; u++){
                ulonglong2 bb = bS[u];
                ADD2(A[u], bb.x); ADD2(B[u], bb.y);
                ADD2(C[u], bb.x); ADD2(D[u], bb.y);
                float2 fix=UPK(A[u]), cox=UPK(B[u]), fiy=UPK(C[u]), coy=UPK(D[u]);
                float2 Co = *(float2*)(cS + u*BATCH + 2*p);
                float Cnx = sigf(fix.x)*Co.x + sigf(fix.y)*tanhf(cox.x);
                float Cny = sigf(fiy.x)*Co.y + sigf(fiy.y)*tanhf(coy.x);
                *(float2*)(cS + u*BATCH + 2*p) = make_float2(Cnx, Cny);
                *(float2*)(g_h0[cw] + (bid*4+u)*BATCH + 2*p) =
                    make_float2(sigf(cox.y)*tanhf(Cnx), sigf(coy.y)*tanhf(Cny));
            }
        }

        grid_sync();   /* the single per-step barrier */

        /* ========= layer 1 (K split 8 ways) + fused out[t-1] ========= */
        const float* h0c = g_h0[cw];
        const float* h1p = g_h1[pv];
        #pragma unroll
        for (int u = 0; u < 4; u++){ A[u]=0; B[u]=0; C[u]=0; D[u]=0; }
        ull o0 = 0, o1 = 0;

        {
            int gi0 = g*GT1;
            const float* s0 = (gi0 < 128) ? h0c + gi0*TF : h1p + (gi0-128)*TF;
            stage_tile(bufg, s0, p);
        }
        for (int kt = 0; kt < GT1; kt++){
            CP_WAIT0();
            GBAR(1+g);
            if (kt+1 < GT1){
                int gi = g*GT1 + kt + 1;
                const float* s = (gi < 128) ? h0c + gi*TF : h1p + (gi-128)*TF;
                stage_tile(bufg + ((kt+1)&1)*TF, s, p);
            }
            const ulonglong2* wp = wS1 + (g*(K1/8) + kt*KT)*4;
            const float* ip = bufg + (kt&1)*TF + 2*p;
            #pragma unroll
            for (int kk = 0; kk < KT; kk++){
                float2 v = *(const float2*)(ip + kk*BATCH);
                ull a0 = PK(v.x, v.x), a1 = PK(v.y, v.y);
                #pragma unroll
                for (int u = 0; u < 4; u++){
                    ulonglong2 w = wp[kk*4 + u];
                    FMA2(A[u], a0, w.x); FMA2(B[u], a0, w.y);
                    FMA2(C[u], a1, w.x); FMA2(D[u], a1, w.y);
                }
                if (g >= 4 && t > 0){
                    ull vp = PK(v.x, v.y);
                    int j = (g-4)*(K1/8) + kt*KT + kk;
                    FMA2(o0, vp, wOutS[j]);
                    FMA2(o1, vp, wOutS[512 + j]);
                }
            }
        }
        __syncthreads();
        if (g > 0){
            int base = (g-1)*64 + p;
            #pragma unroll
            for (int u = 0; u < 4; u++){
                redS[(2*u)*448   + base] = make_ulonglong2(A[u], B[u]);
                redS[(2*u+1)*448 + base] = make_ulonglong2(C[u], D[u]);
            }
        }
        if (g >= 4 && t > 0) oaccS[(g-4)*64 + p] = make_ulonglong2(o0, o1);
        __syncthreads();
        if (g == 0){
            #pragma unroll 1
            for (int s = 0; s < 7; s++){
                int base = s*64 + p;
                #pragma unroll
                for (int u = 0; u < 4; u++){
                    ulonglong2 r0 = redS[(2*u)*448   + base];
                    ulonglong2 r1 = redS[(2*u+1)*448 + base];
                    ADD2(A[u], r0.x); ADD2(B[u], r0.y);
                    ADD2(C[u], r1.x); ADD2(D[u], r1.y);
                }
            }
            #pragma unroll
            for (int u = 0; u < 4; u++){
                ulonglong2 bb = bS[4+u];
                ADD2(A[u], bb.x); ADD2(B[u], bb.y);
                ADD2(C[u], bb.x); ADD2(D[u], bb.y);
                float2 fix=UPK(A[u]), cox=UPK(B[u]), fiy=UPK(C[u]), coy=UPK(D[u]);
                float2 Co = *(float2*)(cS + 512 + u*BATCH + 2*p);
                float Cnx = sigf(fix.x)*Co.x + sigf(fix.y)*tanhf(cox.x);
                float Cny = sigf(fiy.x)*Co.y + sigf(fiy.y)*tanhf(coy.x);
                *(float2*)(cS + 512 + u*BATCH + 2*p) = make_float2(Cnx, Cny);
                *(float2*)(g_h1[cw] + (bid*4+u)*BATCH + 2*p) =
                    make_float2(sigf(cox.y)*tanhf(Cnx), sigf(coy.y)*tanhf(Cny));
            }
        }
        if (g == 1 && t > 0){
            ulonglong2 q = oaccS[p];
            ull s0 = q.x, s1 = q.y;
            #pragma unroll
            for (int s = 1; s < 4; s++){
                q = oaccS[s*64 + p];
                ADD2(s0, q.x); ADD2(s1, q.y);
            }
            float2 r0 = UPK(s0), r1 = UPK(s1);
            float bo0 = b_out[bid*2], bo1 = b_out[bid*2+1];
            size_t ob = ((size_t)(t-1)*BATCH + 2*p)*OUTDIM + bid*2;
            *(float2*)(out + ob)          = make_float2(r0.x + bo0, r1.x + bo1);
            *(float2*)(out + ob + OUTDIM) = make_float2(r0.y + bo0, r1.y + bo1);
        }
    }

    grid_sync();
    /* out[SEQ-1] */
    if (tid < 128){
        int c = tid >> 6, pp = tid & 63;
        ull o = 0;
        const float* h1f = g_h1[(SEQ-1)&1];
        #pragma unroll 4
        for (int j = 0; j < HIDDIM; j++){
            float2 v = __ldcg((const float2*)(h1f + j*BATCH + 2*pp));
            FMA2(o, PK(v.x, v.y), wOutS[c*HIDDIM + j]);
        }
        float2 r = UPK(o);
        float bo = b_out[bid*2 + c];
        size_t ob = ((size_t)(SEQ-1)*BATCH + 2*pp)*OUTDIM + bid*2 + c;
        out[ob]          = r.x + bo;
        out[ob + OUTDIM] = r.y + bo;
    }
    /* final states: [B][HID] each, order h_0, C_0, h_1, C_1 */
    if (g == 0){
        const float* h0f = g_h0[(SEQ-1)&1];
        const float* h1f = g_h1[(SEQ-1)&1];
        #pragma unroll
        for (int u = 0; u < 4; u++){
            int ug = bid*4 + u;
            float2 h0v = __ldcg((const float2*)(h0f + ug*BATCH + 2*p));
            float2 h1v = __ldcg((const float2*)(h1f + ug*BATCH + 2*p));
            float2 c0v = *(float2*)(cS + u*BATCH + 2*p);
            float2 c1v = *(float2*)(cS + 512 + u*BATCH + 2*p);
            size_t r0 = (size_t)(2*p)*HIDDIM + ug, r1 = r0 + HIDDIM;
            out[OB          + r0] = h0v.x;  out[OB          + r1] = h0v.y;
            out[OB +  65536 + r0] = c0v.x;  out[OB +  65536 + r1] = c0v.y;
            out[OB + 131072 + r0] = h1v.x;  out[OB + 131072 + r1] = h1v.y;
            out[OB + 196608 + r0] = c1v.x;  out[OB + 196608 + r1] = c1v.y;
        }
    }
}

extern "C" void kernel_launch(void* const* d_in, const int* in_sizes, int n_in,
                              void* d_out, int out_size)
{
    (void)in_sizes; (void)n_in; (void)out_size;
    const float* x     = (const float*)d_in[0];
    const float* Wg0   = (const float*)d_in[1];
    const float* bg0   = (const float*)d_in[2];
    const float* Wg1   = (const float*)d_in[3];
    const float* bg1   = (const float*)d_in[4];
    const float* W_out = (const float*)d_in[5];
    const float* b_out = (const float*)d_in[6];

    cudaFuncSetAttribute(lstm_persist,
                         cudaFuncAttributeMaxDynamicSharedMemorySize, SMEM_BYTES);

    transpose_x<<<dim3(SEQ, INDIM/32, BATCH/32), dim3(32, 8)>>>(x);
    lstm_persist<<<NBLK, NTHR, SMEM_BYTES>>>(Wg0, bg0, Wg1, bg1, W_out, b_out,
                                             (float*)d_out);
}

// round 11
// speedup vs baseline: 1.8217x; 1.2435x over previous
#include <cuda_runtime.h>
#include <cstdint>
#include <math.h>

#define SEQ 512
#define BATCH 128
#define INDIM 256
#define HIDDIM 512
#define OUTDIM 256
#define K0 768
#define K1 1024
#define NBLK 128
#define NTHR 512
#define KT 8
#define TF (KT*BATCH)               /* 1024 floats = 4KB */
#define GT0 12                      /* tiles per group, layer0 (96 total) */
#define GT1 16                      /* tiles per group, layer1 (128 total) */

#define SM_W0   0
#define SM_W1   (SM_W0 + K0*4*16)            /* 49152  */
#define SM_IN   (SM_W1 + K1*4*16)            /* 114688: 96KB tile window (8g x 3buf x 4KB); redS (64KB) aliases it */
#define SM_OACC (SM_IN + 8*3*TF*4)           /* 212992 */
#define SM_WOUT (SM_OACC + 4*64*16)          /* 217088 */
#define SM_BS   (SM_WOUT + 1024*8)           /* 225280 */
#define SMEM_BYTES (SM_BS + 128)             /* 225408 */

__device__ float g_xT[(size_t)SEQ*INDIM*BATCH];   /* [t][k][b] */
__device__ float g_h0[2][HIDDIM*BATCH];           /* [phase][j][b] */
__device__ float g_h1[2][HIDDIM*BATCH];
__device__ unsigned g_cnt;
__device__ unsigned g_gen;

typedef unsigned long long ull;

__device__ __forceinline__ ull PK(float x, float y){
    ull r; asm("mov.b64 %0, {%1, %2};" : "=l"(r) : "f"(x), "f"(y)); return r;
}
__device__ __forceinline__ float2 UPK(ull a){
    float2 f; asm("mov.b64 {%0, %1}, %2;" : "=f"(f.x), "=f"(f.y) : "l"(a)); return f;
}
#define FMA2(acc,a,w) asm("fma.rn.f32x2 %0, %1, %2, %0;" : "+l"(acc) : "l"(a), "l"(w))
#define ADD2(acc,b)   asm("add.rn.f32x2 %0, %0, %1;"     : "+l"(acc) : "l"(b))

__device__ __forceinline__ void cpa16(float* dst, const float* src){
    unsigned d = (unsigned)__cvta_generic_to_shared(dst);
    asm volatile("cp.async.cg.shared.global [%0], [%1], 16;" :: "r"(d), "l"(src) : "memory");
}
#define CP_COMMIT() asm volatile("cp.async.commit_group;" ::: "memory")
#define CP_WAIT0()  asm volatile("cp.async.wait_group 0;" ::: "memory")
#define CP_WAIT1()  asm volatile("cp.async.wait_group 1;" ::: "memory")
#define GBAR(id)    asm volatile("bar.sync %0, %1;" :: "r"(id), "r"(64) : "memory")

/* one 4KB tile staged by the 64 threads of one K-group: 4 x 16B each */
__device__ __forceinline__ void stage_tile(float* dst, const float* src, int p){
    #pragma unroll
    for (int i = 0; i < 4; i++){
        int off = (i*64 + p)*4;
        cpa16(dst + off, src + off);
    }
    CP_COMMIT();
}

__device__ __forceinline__ float sigf(float x){ return 1.0f/(1.0f+expf(-x)); }

__device__ __forceinline__ void grid_sync(){
    __syncthreads();
    if (threadIdx.x == 0){
        volatile unsigned* vg = &g_gen;
        unsigned gen = *vg;
        __threadfence();
        if (atomicAdd(&g_cnt, 1u) == NBLK-1u){
            atomicExch(&g_cnt, 0u);
            __threadfence();
            atomicAdd(&g_gen, 1u);
        } else {
            while (*vg == gen) { __nanosleep(20); }
        }
        __threadfence();
    }
    __syncthreads();
}

/* x [t][b][k] -> g_xT [t][k][b] */
__global__ void transpose_x(const float* __restrict__ x){
    __shared__ float tile[32][33];
    int t = blockIdx.x, k0 = blockIdx.y*32, b0 = blockIdx.z*32;
    const float* src = x + (size_t)t*BATCH*INDIM;
    #pragma unroll
    for (int i = threadIdx.y; i < 32; i += 8)
        tile[i][threadIdx.x] = src[(size_t)(b0+i)*INDIM + k0 + threadIdx.x];
    __syncthreads();
    float* dst = g_xT + (size_t)t*INDIM*BATCH;
    #pragma unroll
    for (int i = threadIdx.y; i < 32; i += 8)
        dst[(size_t)(k0+i)*BATCH + b0 + threadIdx.x] = tile[threadIdx.x][i];
}

__global__ void __launch_bounds__(NTHR, 1) lstm_persist(
    const float* __restrict__ Wg0, const float* __restrict__ bg0,
    const float* __restrict__ Wg1, const float* __restrict__ bg1,
    const float* __restrict__ W_out, const float* __restrict__ b_out,
    float* __restrict__ out)
{
    extern __shared__ char smem[];
    ulonglong2* wS0  = (ulonglong2*)(smem + SM_W0);   /* [k*4+u] = {(wf,wi),(wc,wo)} */
    ulonglong2* wS1  = (ulonglong2*)(smem + SM_W1);
    float*      inS  = (float*)(smem + SM_IN);        /* tiles: (g*3+s)*TF */
    ulonglong2* redS = (ulonglong2*)(smem + SM_IN);   /* ALIAS: [g*512 + u*128 + b] = (fi, co) */
    ulonglong2* oaccS= (ulonglong2*)(smem + SM_OACC); /* [(g-4)*64+p] = (o0,o1) */
    ull*        wOutS= (ull*)(smem + SM_WOUT);        /* [c*512+j] = (w,w) dup */
    ulonglong2* bS   = (ulonglong2*)(smem + SM_BS);   /* [layer*4+u] = (bfi,bco) */

    const int tid = threadIdx.x, bid = blockIdx.x;
    const int g   = tid >> 6;           /* K-group 0..7 */
    const int p   = tid & 63;           /* batch pair: 2p, 2p+1 */
    const int uo  = tid >> 7;           /* owner unit 0..3 */
    const int bo  = tid & 127;          /* owner batch */

    /* ---- weights / consts -> smem ---- */
    for (int idx = tid; idx < K0*4; idx += NTHR){
        int k = idx >> 2, uu = bid*4 + (idx & 3);
        float wf = Wg0[(size_t)(0*HIDDIM+uu)*K0 + k];
        float wi = Wg0[(size_t)(1*HIDDIM+uu)*K0 + k];
        float wc = Wg0[(size_t)(2*HIDDIM+uu)*K0 + k];
        float wo = Wg0[(size_t)(3*HIDDIM+uu)*K0 + k];
        wS0[idx] = make_ulonglong2(PK(wf,wi), PK(wc,wo));
    }
    for (int idx = tid; idx < K1*4; idx += NTHR){
        int k = idx >> 2, uu = bid*4 + (idx & 3);
        float wf = Wg1[(size_t)(0*HIDDIM+uu)*K1 + k];
        float wi = Wg1[(size_t)(1*HIDDIM+uu)*K1 + k];
        float wc = Wg1[(size_t)(2*HIDDIM+uu)*K1 + k];
        float wo = Wg1[(size_t)(3*HIDDIM+uu)*K1 + k];
        wS1[idx] = make_ulonglong2(PK(wf,wi), PK(wc,wo));
    }
    for (int idx = tid; idx < 2*HIDDIM; idx += NTHR){
        int c = idx >> 9, j = idx & 511;
        float w = W_out[(size_t)(bid*2+c)*HIDDIM + j];
        wOutS[idx] = PK(w, w);
    }
    if (tid < 8){
        int L = tid >> 2, u = tid & 3, ug = bid*4 + u;
        const float* bg = L ? bg1 : bg0;
        bS[tid] = make_ulonglong2(PK(bg[ug], bg[HIDDIM+ug]),
                                  PK(bg[2*HIDDIM+ug], bg[3*HIDDIM+ug]));
    }
    if (g == 0){
        float2 z = make_float2(0.f, 0.f);
        #pragma unroll
        for (int u = 0; u < 4; u++){
            int o2 = (bid*4+u)*BATCH + 2*p;
            *(float2*)(g_h0[0]+o2) = z; *(float2*)(g_h0[1]+o2) = z;
            *(float2*)(g_h1[0]+o2) = z; *(float2*)(g_h1[1]+o2) = z;
        }
    }
    /* owner state */
    float C0own = 0.f, C1own = 0.f, h0own = 0.f, h1own = 0.f;

    grid_sync();

    const size_t OB = (size_t)SEQ*BATCH*OUTDIM;
    float* tA = inS + (g*3 + 0)*TF;
    float* tB = inS + (g*3 + 1)*TF;
    float* tC = inS + (g*3 + 2)*TF;

    for (int t = 0; t < SEQ; t++){
        const int cw = t & 1, pv = cw ^ 1;

        /* ================= layer 0 (K split 8 ways) ================= */
        const float* xb  = g_xT + (size_t)t*INDIM*BATCH;
        const float* h0p = g_h0[pv];
        ull A[4]={0,0,0,0}, B[4]={0,0,0,0}, C[4]={0,0,0,0}, D[4]={0,0,0,0};

        {
            int j0 = g*GT0, j1 = j0 + 1;
            stage_tile(tA, (j0 < 32) ? xb + j0*TF : h0p + (j0-32)*TF, p);
            stage_tile(tB, (j1 < 32) ? xb + j1*TF : h0p + (j1-32)*TF, p);
        }
        const ulonglong2* wp = wS0 + (g*96)*4;
        float *b0 = tA, *b1 = tB, *b2 = tC;
        for (int kt = 0; kt < GT0; kt++){
            if (kt == GT0-1) { CP_WAIT0(); } else { CP_WAIT1(); }
            GBAR(1+g);
            if (kt+2 < GT0){
                int j = g*GT0 + kt + 2;
                stage_tile(b2, (j < 32) ? xb + j*TF : h0p + (j-32)*TF, p);
            }
            const float* ip = b0 + 2*p;
            #pragma unroll
            for (int kk = 0; kk < KT; kk++){
                float2 v = *(const float2*)(ip + kk*BATCH);
                ull a0 = PK(v.x, v.x), a1 = PK(v.y, v.y);
                #pragma unroll
                for (int u = 0; u < 4; u++){
                    ulonglong2 w = wp[kk*4 + u];
                    FMA2(A[u], a0, w.x); FMA2(B[u], a0, w.y);
                    FMA2(C[u], a1, w.x); FMA2(D[u], a1, w.y);
                }
            }
            wp += KT*4;
            float* tmp = b0; b0 = b1; b1 = b2; b2 = tmp;
        }
        __syncthreads();
        {
            int base = g*512 + 2*p;   /* + u*128 */
            #pragma unroll
            for (int u = 0; u < 4; u++){
                redS[base + u*128]     = make_ulonglong2(A[u], B[u]);
                redS[base + u*128 + 1] = make_ulonglong2(C[u], D[u]);
            }
        }
        __syncthreads();
        {   /* balanced: each thread owns (uo, bo) */
            ull fi = 0, co = 0;
            int slot = uo*128 + bo;
            #pragma unroll
            for (int gg = 0; gg < 8; gg++){
                ulonglong2 r = redS[gg*512 + slot];
                ADD2(fi, r.x); ADD2(co, r.y);
            }
            ulonglong2 bb = bS[uo];
            ADD2(fi, bb.x); ADD2(co, bb.y);
            float2 q1 = UPK(fi), q2 = UPK(co);
            C0own = sigf(q1.x)*C0own + sigf(q1.y)*tanhf(q2.x);
            h0own = sigf(q2.y)*tanhf(C0own);
            g_h0[cw][(bid*4+uo)*BATCH + bo] = h0own;
        }

        grid_sync();   /* the single per-step grid barrier */

        /* ========= layer 1 (K split 8 ways) + fused out[t-1] ========= */
        const float* h0c = g_h0[cw];
        const float* h1p = g_h1[pv];
        #pragma unroll
        for (int u = 0; u < 4; u++){ A[u]=0; B[u]=0; C[u]=0; D[u]=0; }
        ull o0 = 0, o1 = 0;

        {
            int j0 = g*GT1, j1 = j0 + 1;
            stage_tile(tA, (j0 < 64) ? h0c + j0*TF : h1p + (j0-64)*TF, p);
            stage_tile(tB, (j1 < 64) ? h0c + j1*TF : h1p + (j1-64)*TF, p);
        }
        wp = wS1 + (g*128)*4;
        b0 = tA; b1 = tB; b2 = tC;
        for (int kt = 0; kt < GT1; kt++){
            if (kt == GT1-1) { CP_WAIT0(); } else { CP_WAIT1(); }
            GBAR(1+g);
            if (kt+2 < GT1){
                int j = g*GT1 + kt + 2;
                stage_tile(b2, (j < 64) ? h0c + j*TF : h1p + (j-64)*TF, p);
            }
            const float* ip = b0 + 2*p;
            #pragma unroll
            for (int kk = 0; kk < KT; kk++){
                float2 v = *(const float2*)(ip + kk*BATCH);
                ull a0 = PK(v.x, v.x), a1 = PK(v.y, v.y);
                #pragma unroll
                for (int u = 0; u < 4; u++){
                    ulonglong2 w = wp[kk*4 + u];
                    FMA2(A[u], a0, w.x); FMA2(B[u], a0, w.y);
                    FMA2(C[u], a1, w.x); FMA2(D[u], a1, w.y);
                }
                if (g >= 4 && t > 0){
                    ull vp = PK(v.x, v.y);
                    int j = (g-4)*128 + kt*KT + kk;
                    FMA2(o0, vp, wOutS[j]);
                    FMA2(o1, vp, wOutS[512 + j]);
                }
            }
            wp += KT*4;
            float* tmp = b0; b0 = b1; b1 = b2; b2 = tmp;
        }
        __syncthreads();
        {
            int base = g*512 + 2*p;
            #pragma unroll
            for (int u = 0; u < 4; u++){
                redS[base + u*128]     = make_ulonglong2(A[u], B[u]);
                redS[base + u*128 + 1] = make_ulonglong2(C[u], D[u]);
            }
            if (g >= 4 && t > 0) oaccS[(g-4)*64 + p] = make_ulonglong2(o0, o1);
        }
        __syncthreads();
        {
            ull fi = 0, co = 0;
            int slot = uo*128 + bo;
            #pragma unroll
            for (int gg = 0; gg < 8; gg++){
                ulonglong2 r = redS[gg*512 + slot];
                ADD2(fi, r.x); ADD2(co, r.y);
            }
            ulonglong2 bb = bS[4+uo];
            ADD2(fi, bb.x); ADD2(co, bb.y);
            float2 q1 = UPK(fi), q2 = UPK(co);
            C1own = sigf(q1.x)*C1own + sigf(q1.y)*tanhf(q2.x);
            h1own = sigf(q2.y)*tanhf(C1own);
            g_h1[cw][(bid*4+uo)*BATCH + bo] = h1own;
        }
        if (g == 1 && t > 0){
            ulonglong2 q = oaccS[p];
            ull s0 = q.x, s1 = q.y;
            #pragma unroll
            for (int s = 1; s < 4; s++){
                q = oaccS[s*64 + p];
                ADD2(s0, q.x); ADD2(s1, q.y);
            }
            float2 r0 = UPK(s0), r1 = UPK(s1);
            float bo0 = b_out[bid*2], bo1 = b_out[bid*2+1];
            size_t ob = ((size_t)(t-1)*BATCH + 2*p)*OUTDIM + bid*2;
            *(float2*)(out + ob)          = make_float2(r0.x + bo0, r1.x + bo1);
            *(float2*)(out + ob + OUTDIM) = make_float2(r0.y + bo0, r1.y + bo1);
        }
        __syncthreads();   /* protect redS/tile alias before next step's staging */
    }

    grid_sync();
    /* out[SEQ-1] */
    if (tid < 128){
        int c = tid >> 6, pp = tid & 63;
        ull o = 0;
        const float* h1f = g_h1[(SEQ-1)&1];
        #pragma unroll 4
        for (int j = 0; j < HIDDIM; j++){
            float2 v = __ldcg((const float2*)(h1f + j*BATCH + 2*pp));
            FMA2(o, PK(v.x, v.y), wOutS[c*HIDDIM + j]);
        }
        float2 r = UPK(o);
        float bo2 = b_out[bid*2 + c];
        size_t ob = ((size_t)(SEQ-1)*BATCH + 2*pp)*OUTDIM + bid*2 + c;
        out[ob]          = r.x + bo2;
        out[ob + OUTDIM] = r.y + bo2;
    }
    /* final states: [B][HID] each, order h_0, C_0, h_1, C_1 (owner threads) */
    {
        size_t r = (size_t)bo*HIDDIM + bid*4 + uo;
        out[OB          + r] = h0own;
        out[OB +  65536 + r] = C0own;
        out[OB + 131072 + r] = h1own;
        out[OB + 196608 + r] = C1own;
    }
}

extern "C" void kernel_launch(void* const* d_in, const int* in_sizes, int n_in,
                              void* d_out, int out_size)
{
    (void)in_sizes; (void)n_in; (void)out_size;
    const float* x     = (const float*)d_in[0];
    const float* Wg0   = (const float*)d_in[1];
    const float* bg0   = (const float*)d_in[2];
    const float* Wg1   = (const float*)d_in[3];
    const float* bg1   = (const float*)d_in[4];
    const float* W_out = (const float*)d_in[5];
    const float* b_out = (const float*)d_in[6];

    cudaFuncSetAttribute(lstm_persist,
                         cudaFuncAttributeMaxDynamicSharedMemorySize, SMEM_BYTES);

    transpose_x<<<dim3(SEQ, INDIM/32, BATCH/32), dim3(32, 8)>>>(x);
    lstm_persist<<<NBLK, NTHR, SMEM_BYTES>>>(Wg0, bg0, Wg1, bg1, W_out, b_out,
                                             (float*)d_out);
}